// round 9
// baseline (speedup 1.0000x reference)
#include <cuda_runtime.h>
#include <cuda_fp16.h>
#include <cstdint>

// ---------------- problem constants ----------------
#define BATCH 4096
#define DIM   2048
#define NK    8
#define H2    64

// ---------------- tiling ----------------
#define BM     64
#define BN     128
#define KC     32
#define NCHUNK (DIM / KC)        // 64
#define GX     (DIM / BN)        // 16 d-blocks
#define GYT    72                // max m-tiles (worst case 64+8)
#define NSTAGE 3

#define PITCH_B 80               // bytes per smem row (64 data + 16 pad)
#define A_T     (BM * PITCH_B)   // 5120
#define B_T     (BN * PITCH_B)   // 10240
#define STAGE_B (A_T + B_T)      // 15360
#define SMEM_TOTAL (NSTAGE * STAGE_B)   // 46080 (x4 CTAs = 184320 <= 228KB/SM)

// ---------------- device scratch (no allocation allowed) ----------------
__device__ int g_perm[BATCH];
__device__ int g_tile_k[GYT];
__device__ int g_tile_row0[GYT];
__device__ int g_tile_rend[GYT];
__device__ int g_ntiles;
// pre-converted fp16 operands (packed uint4 = 8 elements)
__device__ uint4 g_xh[BATCH * DIM / 8];               // 16.8 MB
__device__ uint4 g_wh[(size_t)NK * DIM * DIM / 8];    // 67 MB, regrouped [k][d][j]

// ---------------- PTX helpers ----------------
__device__ __forceinline__ uint32_t smem_u32(const void* p) {
    uint32_t a;
    asm("{ .reg .u64 t; cvta.to.shared.u64 t, %1; cvt.u32.u64 %0, t; }" : "=r"(a) : "l"(p));
    return a;
}

__device__ __forceinline__ void cpasync16(uint32_t dst, const void* src) {
    asm volatile("{ .reg .u64 g; cvta.to.global.u64 g, %1; "
                 "cp.async.cg.shared.global [%0], [g], 16; }"
                 :: "r"(dst), "l"(src) : "memory");
}
#define CP_COMMIT() asm volatile("cp.async.commit_group;" ::: "memory")
#define CP_WAIT1()  asm volatile("cp.async.wait_group 1;" ::: "memory")

__device__ __forceinline__ void ldsm4(uint32_t* r, uint32_t addr) {
    asm volatile("ldmatrix.sync.aligned.m8n8.x4.shared.b16 {%0,%1,%2,%3}, [%4];"
                 : "=r"(r[0]), "=r"(r[1]), "=r"(r[2]), "=r"(r[3]) : "r"(addr));
}

__device__ __forceinline__ void mma_f16(float* c, const uint32_t* a, const uint32_t* b) {
    asm volatile(
        "mma.sync.aligned.m16n8k16.row.col.f32.f16.f16.f32 "
        "{%0,%1,%2,%3}, {%4,%5,%6,%7}, {%8,%9}, {%0,%1,%2,%3};"
        : "+f"(c[0]), "+f"(c[1]), "+f"(c[2]), "+f"(c[3])
        : "r"(a[0]), "r"(a[1]), "r"(a[2]), "r"(a[3]), "r"(b[0]), "r"(b[1]));
}

__device__ __forceinline__ uint32_t packh2(float f0, float f1) {
    __half2 p = __floats2half2_rn(f0, f1);
    return *reinterpret_cast<uint32_t*>(&p);
}

// ---------------- prep: sort by intention, tile table, t2, out init ----------------
__global__ void __launch_bounds__(1024) prep_kernel(
    const float* __restrict__ intention, const float* __restrict__ W2,
    const float* __restrict__ b2, const float* __restrict__ W3,
    const float* __restrict__ b3, float* __restrict__ out) {
    __shared__ int cnt[NK], cur[NK];
    __shared__ float t2s[NK];
    int t = threadIdx.x;
    if (t < NK) cnt[t] = 0;
    __syncthreads();

    int myk[4];
#pragma unroll
    for (int i = 0; i < 4; i++) {
        int b = t + i * 1024;
        const float4* p = (const float4*)(intention + (size_t)b * NK);
        float4 v0 = p[0], v1 = p[1];
        int k = 0;
        if (v0.y > 0.5f) k = 1;
        if (v0.z > 0.5f) k = 2;
        if (v0.w > 0.5f) k = 3;
        if (v1.x > 0.5f) k = 4;
        if (v1.y > 0.5f) k = 5;
        if (v1.z > 0.5f) k = 6;
        if (v1.w > 0.5f) k = 7;
        myk[i] = k;
        atomicAdd(&cnt[k], 1);
    }
    __syncthreads();

    if (t == 0) {
        int off = 0, nt = 0;
        for (int k = 0; k < NK; k++) {
            int c = cnt[k];
            for (int r = 0; r < c; r += BM) {
                g_tile_k[nt] = k;
                g_tile_row0[nt] = off + r;
                g_tile_rend[nt] = off + c;
                nt++;
            }
            cur[k] = off;
            off += c;
        }
        g_ntiles = nt;
    }
    if (t < NK) {
        float s = 0.f;
        for (int h = 0; h < H2; h++) {
            float v = W2[h * NK + t] + b2[h];
            s += fmaxf(v, 0.f) * W3[DIM + h];
        }
        t2s[t] = s;
    }
    __syncthreads();

    float bias = b3[0];
#pragma unroll
    for (int i = 0; i < 4; i++) {
        int b = t + i * 1024;
        int pos = atomicAdd(&cur[myk[i]], 1);
        g_perm[pos] = b;
        out[b] = bias + t2s[myk[i]];
    }
}

// ---------------- pre-pass converters ----------------
__global__ void __launch_bounds__(256) cvt_x_kernel(const float* __restrict__ x) {
    int row = blockIdx.x;
    int t   = threadIdx.x;
    const float4* src = (const float4*)x + (size_t)row * (DIM / 4) + t * 2;
    float4 v0 = src[0], v1 = src[1];
    uint4 h;
    h.x = packh2(v0.x, v0.y);
    h.y = packh2(v0.z, v0.w);
    h.z = packh2(v1.x, v1.y);
    h.w = packh2(v1.z, v1.w);
    g_xh[(size_t)row * (DIM / 8) + t] = h;
}

__global__ void __launch_bounds__(256) cvt_w_kernel(const float* __restrict__ W1) {
    int r = blockIdx.x;            // row = d*8+k
    int t = threadIdx.x;
    int d = r >> 3, k = r & 7;
    const float4* src = (const float4*)W1 + (size_t)r * (DIM / 4) + t * 2;
    float4 v0 = src[0], v1 = src[1];
    uint4 h;
    h.x = packh2(v0.x, v0.y);
    h.y = packh2(v0.z, v0.w);
    h.z = packh2(v1.x, v1.y);
    h.w = packh2(v1.z, v1.w);
    g_wh[((size_t)k * DIM + d) * (DIM / 8) + t] = h;   // regroup by branch k
}

// ---------------- fused grouped HMMA GEMM (fp16, 3-stage, 4 CTAs/SM) ----------------
__global__ void __launch_bounds__(256, 4) gemm_kernel(
    const float* __restrict__ b1, const float* __restrict__ W3,
    float* __restrict__ out) {
    int tile = blockIdx.x;
    if (tile >= g_ntiles) return;
    int k     = g_tile_k[tile];
    int row0  = g_tile_row0[tile];
    int rend  = g_tile_rend[tile];
    int dbase = blockIdx.y * BN;

    extern __shared__ char smem[];
    uint32_t sb = smem_u32(smem);
    int t    = threadIdx.x;
    int lane = t & 31;
    int wid  = t >> 5;
    int mw   = wid & 1;            // 2 warp-rows of 32
    int nw   = wid >> 1;           // 4 warp-cols of 32

    // ---- A loader: 4 threads per row, 1 x 16B seg each ----
    int ar = t >> 2, aseg = t & 3;
    int pr = row0 + ar;
    int samp = (pr < rend) ? g_perm[pr] : g_perm[row0];
    const uint4* ah = g_xh + (size_t)samp * (DIM / 8) + aseg;
    uint32_t adst = (uint32_t)ar * PITCH_B + (uint32_t)aseg * 16u;

    // ---- B loader: 2 transfers per thread ----
    const uint4* bw = g_wh + ((size_t)k * DIM + dbase) * (DIM / 8);
    uint32_t boff[2], bdst[2];
#pragma unroll
    for (int j = 0; j < 2; j++) {
        int idx = t + j * 256;
        int br = idx >> 2, bs = idx & 3;
        boff[j] = (uint32_t)br * (DIM / 8) + (uint32_t)bs;
        bdst[j] = (uint32_t)br * PITCH_B + (uint32_t)bs * 16u;
    }

    // ---- ldmatrix lane base offsets ----
    uint32_t a_base = ((uint32_t)(mw * 32 + (lane & 7) + 8 * ((lane >> 3) & 1))) * PITCH_B
                    + (uint32_t)(lane >> 4) * 16u;
    uint32_t b_base = ((uint32_t)(nw * 32 + (lane & 7) + 8 * ((lane >> 3) >> 1))) * PITCH_B
                    + (uint32_t)((lane >> 3) & 1) * 16u;

    float acc[2][4][4];
#pragma unroll
    for (int i = 0; i < 2; i++)
#pragma unroll
        for (int j = 0; j < 4; j++)
#pragma unroll
            for (int e = 0; e < 4; e++) acc[i][j][e] = 0.f;

    auto issue = [&](int c, uint32_t st) {
        if (c < NCHUNK) {
            uint32_t c4 = (uint32_t)c * 4u;
            cpasync16(st + adst, ah + c4);
#pragma unroll
            for (int j = 0; j < 2; j++)
                cpasync16(st + A_T + bdst[j], bw + boff[j] + c4);
        }
        CP_COMMIT();
    };

    issue(0, sb);
    issue(1, sb + STAGE_B);

    int cs = 0;   // compute stage
    int is = 2;   // issue stage
#pragma unroll 1
    for (int c = 0; c < NCHUNK; c++) {
        CP_WAIT1();
        __syncthreads();
        issue(c + 2, sb + (uint32_t)is * STAGE_B);
        uint32_t st = sb + (uint32_t)cs * STAGE_B;

#pragma unroll
        for (int ks = 0; ks < 2; ks++) {
            uint32_t ko = (uint32_t)ks * 32u;
            uint32_t Ah[2][4];
#pragma unroll
            for (int i = 0; i < 2; i++)
                ldsm4(Ah[i], st + a_base + (uint32_t)i * (16u * PITCH_B) + ko);
#pragma unroll
            for (int jp = 0; jp < 2; jp++) {
                uint32_t B[4];
                ldsm4(B, st + A_T + b_base + (uint32_t)jp * (16u * PITCH_B) + ko);
#pragma unroll
                for (int i = 0; i < 2; i++) {
                    mma_f16(acc[i][jp * 2],     Ah[i], &B[0]);
                    mma_f16(acc[i][jp * 2 + 1], Ah[i], &B[2]);
                }
            }
        }
        cs = (cs == 2) ? 0 : cs + 1;
        is = (is == 2) ? 0 : is + 1;
    }

    // ---- fused epilogue: relu(acc + b1) * W3, row-reduce, atomicAdd ----
#pragma unroll
    for (int i = 0; i < 2; i++) {
        float s0 = 0.f, s1 = 0.f;
#pragma unroll
        for (int j = 0; j < 4; j++) {
            int d = dbase + nw * 32 + j * 8 + 2 * (lane & 3);
            float bb0 = __ldg(&b1[(size_t)d * NK + k]);
            float bb1 = __ldg(&b1[(size_t)(d + 1) * NK + k]);
            float w30 = __ldg(&W3[d]);
            float w31 = __ldg(&W3[d + 1]);
            s0 = fmaf(fmaxf(acc[i][j][0] + bb0, 0.f), w30, s0);
            s0 = fmaf(fmaxf(acc[i][j][1] + bb1, 0.f), w31, s0);
            s1 = fmaf(fmaxf(acc[i][j][2] + bb0, 0.f), w30, s1);
            s1 = fmaf(fmaxf(acc[i][j][3] + bb1, 0.f), w31, s1);
        }
        s0 += __shfl_xor_sync(0xFFFFFFFFu, s0, 1);
        s0 += __shfl_xor_sync(0xFFFFFFFFu, s0, 2);
        s1 += __shfl_xor_sync(0xFFFFFFFFu, s1, 1);
        s1 += __shfl_xor_sync(0xFFFFFFFFu, s1, 2);
        if ((lane & 3) == 0) {
            int m0 = mw * 32 + i * 16 + (lane >> 2);
            int pr0 = row0 + m0;
            int pr1 = pr0 + 8;
            if (pr0 < rend) atomicAdd(&out[g_perm[pr0]], s0);
            if (pr1 < rend) atomicAdd(&out[g_perm[pr1]], s1);
        }
    }
}

// ---------------- launch ----------------
extern "C" void kernel_launch(void* const* d_in, const int* in_sizes, int n_in,
                              void* d_out, int out_size) {
    const float* x         = (const float*)d_in[0];
    const float* intention = (const float*)d_in[1];
    const float* W1        = (const float*)d_in[2];
    const float* b1        = (const float*)d_in[3];
    const float* W2        = (const float*)d_in[4];
    const float* b2        = (const float*)d_in[5];
    const float* W3        = (const float*)d_in[6];
    const float* b3        = (const float*)d_in[7];
    float* out             = (float*)d_out;

    cudaFuncSetAttribute(gemm_kernel, cudaFuncAttributeMaxDynamicSharedMemorySize,
                         SMEM_TOTAL);

    prep_kernel<<<1, 1024>>>(intention, W2, b2, W3, b3, out);
    cvt_x_kernel<<<BATCH, 256>>>(x);
    cvt_w_kernel<<<DIM * NK, 256>>>(W1);
    gemm_kernel<<<dim3(GYT, GX), 256, SMEM_TOTAL>>>(b1, W3, out);
}

// round 10
// speedup vs baseline: 1.7946x; 1.7946x over previous
#include <cuda_runtime.h>
#include <cuda_fp16.h>
#include <cstdint>

// ---------------- problem constants ----------------
#define BATCH 4096
#define DIM   2048
#define NK    8
#define H2    64

// ---------------- tiling ----------------
#define BM     64
#define BN     128
#define KC     64
#define NCHUNK (DIM / KC)        // 32
#define GX     (DIM / BN)        // 16 d-blocks
#define GYT    72                // max m-tiles (worst case 64+8)
#define NSTAGE 3

// 128-byte rows, XOR-swizzled (Swizzle<3,4,3>), no padding
#define ROW_B   128
#define A_T     (BM * ROW_B)     // 8192
#define B_T     (BN * ROW_B)     // 16384
#define STAGE_B (A_T + B_T)      // 24576
#define SMEM_TOTAL (NSTAGE * STAGE_B)   // 73728 (x3 CTAs = 221184 <= 228KB/SM)

// ---------------- device scratch (no allocation allowed) ----------------
__device__ int g_perm[BATCH];
__device__ int g_tile_k[GYT];
__device__ int g_tile_row0[GYT];
__device__ int g_tile_rend[GYT];
__device__ int g_ntiles;
// pre-converted fp16 operands (packed uint4 = 8 elements)
__device__ uint4 g_xh[BATCH * DIM / 8];               // 16.8 MB
__device__ uint4 g_wh[(size_t)NK * DIM * DIM / 8];    // 67 MB, regrouped [k][d][j]

// ---------------- PTX helpers ----------------
__device__ __forceinline__ uint32_t smem_u32(const void* p) {
    uint32_t a;
    asm("{ .reg .u64 t; cvta.to.shared.u64 t, %1; cvt.u32.u64 %0, t; }" : "=r"(a) : "l"(p));
    return a;
}

__device__ __forceinline__ void cpasync16(uint32_t dst, const void* src) {
    asm volatile("{ .reg .u64 g; cvta.to.global.u64 g, %1; "
                 "cp.async.cg.shared.global [%0], [g], 16; }"
                 :: "r"(dst), "l"(src) : "memory");
}
#define CP_COMMIT() asm volatile("cp.async.commit_group;" ::: "memory")
#define CP_WAIT1()  asm volatile("cp.async.wait_group 1;" ::: "memory")

__device__ __forceinline__ void ldsm4(uint32_t* r, uint32_t addr) {
    asm volatile("ldmatrix.sync.aligned.m8n8.x4.shared.b16 {%0,%1,%2,%3}, [%4];"
                 : "=r"(r[0]), "=r"(r[1]), "=r"(r[2]), "=r"(r[3]) : "r"(addr));
}

__device__ __forceinline__ void mma_f16(float* c, const uint32_t* a, const uint32_t* b) {
    asm volatile(
        "mma.sync.aligned.m16n8k16.row.col.f32.f16.f16.f32 "
        "{%0,%1,%2,%3}, {%4,%5,%6,%7}, {%8,%9}, {%0,%1,%2,%3};"
        : "+f"(c[0]), "+f"(c[1]), "+f"(c[2]), "+f"(c[3])
        : "r"(a[0]), "r"(a[1]), "r"(a[2]), "r"(a[3]), "r"(b[0]), "r"(b[1]));
}

__device__ __forceinline__ uint32_t packh2(float f0, float f1) {
    __half2 p = __floats2half2_rn(f0, f1);
    return *reinterpret_cast<uint32_t*>(&p);
}

// ---------------- prep: sort by intention, tile table, t2, out init ----------------
__global__ void __launch_bounds__(1024) prep_kernel(
    const float* __restrict__ intention, const float* __restrict__ W2,
    const float* __restrict__ b2, const float* __restrict__ W3,
    const float* __restrict__ b3, float* __restrict__ out) {
    __shared__ int cnt[NK], cur[NK];
    __shared__ float t2s[NK];
    int t = threadIdx.x;
    if (t < NK) cnt[t] = 0;
    __syncthreads();

    int myk[4];
#pragma unroll
    for (int i = 0; i < 4; i++) {
        int b = t + i * 1024;
        const float4* p = (const float4*)(intention + (size_t)b * NK);
        float4 v0 = p[0], v1 = p[1];
        int k = 0;
        if (v0.y > 0.5f) k = 1;
        if (v0.z > 0.5f) k = 2;
        if (v0.w > 0.5f) k = 3;
        if (v1.x > 0.5f) k = 4;
        if (v1.y > 0.5f) k = 5;
        if (v1.z > 0.5f) k = 6;
        if (v1.w > 0.5f) k = 7;
        myk[i] = k;
        atomicAdd(&cnt[k], 1);
    }
    __syncthreads();

    if (t == 0) {
        int off = 0, nt = 0;
        for (int k = 0; k < NK; k++) {
            int c = cnt[k];
            for (int r = 0; r < c; r += BM) {
                g_tile_k[nt] = k;
                g_tile_row0[nt] = off + r;
                g_tile_rend[nt] = off + c;
                nt++;
            }
            cur[k] = off;
            off += c;
        }
        g_ntiles = nt;
    }
    if (t < NK) {
        float s = 0.f;
        for (int h = 0; h < H2; h++) {
            float v = W2[h * NK + t] + b2[h];
            s += fmaxf(v, 0.f) * W3[DIM + h];
        }
        t2s[t] = s;
    }
    __syncthreads();

    float bias = b3[0];
#pragma unroll
    for (int i = 0; i < 4; i++) {
        int b = t + i * 1024;
        int pos = atomicAdd(&cur[myk[i]], 1);
        g_perm[pos] = b;
        out[b] = bias + t2s[myk[i]];
    }
}

// ---------------- pre-pass converter (x and W1 in one launch) ----------------
__global__ void __launch_bounds__(256) cvt_kernel(const float* __restrict__ x,
                                                  const float* __restrict__ W1) {
    int blk = blockIdx.x;
    int t   = threadIdx.x;
    if (blk < BATCH) {
        const float4* src = (const float4*)x + (size_t)blk * (DIM / 4) + t * 2;
        float4 v0 = src[0], v1 = src[1];
        uint4 h;
        h.x = packh2(v0.x, v0.y);
        h.y = packh2(v0.z, v0.w);
        h.z = packh2(v1.x, v1.y);
        h.w = packh2(v1.z, v1.w);
        g_xh[(size_t)blk * (DIM / 8) + t] = h;
    } else {
        int r = blk - BATCH;           // W1 row = d*8+k
        int d = r >> 3, k = r & 7;
        const float4* src = (const float4*)W1 + (size_t)r * (DIM / 4) + t * 2;
        float4 v0 = src[0], v1 = src[1];
        uint4 h;
        h.x = packh2(v0.x, v0.y);
        h.y = packh2(v0.z, v0.w);
        h.z = packh2(v1.x, v1.y);
        h.w = packh2(v1.z, v1.w);
        g_wh[((size_t)k * DIM + d) * (DIM / 8) + t] = h;   // regroup by branch k
    }
}

// ---------------- fused grouped HMMA GEMM (fp16, KC=64 swizzled, 3 CTAs/SM) ----------------
__global__ void __launch_bounds__(256, 3) gemm_kernel(
    const float* __restrict__ b1, const float* __restrict__ W3,
    float* __restrict__ out) {
    int tile = blockIdx.x;
    if (tile >= g_ntiles) return;
    int k     = g_tile_k[tile];
    int row0  = g_tile_row0[tile];
    int rend  = g_tile_rend[tile];
    int dbase = blockIdx.y * BN;

    extern __shared__ char smem[];
    uint32_t sb = smem_u32(smem);
    int t    = threadIdx.x;
    int lane = t & 31;
    int wid  = t >> 5;
    int mw   = wid & 1;            // 2 warp-rows of 32
    int nw   = wid >> 1;           // 4 warp-cols of 32

    // ---- A loader: 2 granules per thread (rows t>>3 and t>>3+32) ----
    const uint4* ah[2];
    uint32_t adst[2];
#pragma unroll
    for (int j = 0; j < 2; j++) {
        int idx  = t + j * 256;
        int row  = idx >> 3, gran = idx & 7;
        int pr   = row0 + row;
        int samp = (pr < rend) ? g_perm[pr] : g_perm[row0];
        ah[j]   = g_xh + (size_t)samp * (DIM / 8) + gran;
        adst[j] = (uint32_t)row * ROW_B + (uint32_t)((gran ^ (row & 7)) << 4);
    }
    // ---- B loader: 4 granules per thread ----
    const uint4* bw = g_wh + ((size_t)k * DIM + dbase) * (DIM / 8);
    uint32_t boff[4], bdst[4];
#pragma unroll
    for (int j = 0; j < 4; j++) {
        int idx = t + j * 256;
        int row = idx >> 3, gran = idx & 7;
        boff[j] = (uint32_t)row * (DIM / 8) + (uint32_t)gran;
        bdst[j] = (uint32_t)row * ROW_B + (uint32_t)((gran ^ (row & 7)) << 4);
    }

    // ---- ldmatrix lane mapping (swizzled) ----
    int g       = lane >> 3;
    uint32_t xr = (uint32_t)(lane & 7);               // XOR key (row&7 == lane&7)
    // A: rows mw*32 + i*16 + (lane&7) + 8*(g&1), 16B-slot = g>>1
    uint32_t a_row  = (uint32_t)(mw * 32 + (lane & 7) + 8 * (g & 1));
    uint32_t a_slot = (uint32_t)(g >> 1);
    // B: rows nw*32 + jp*16 + (lane&7) + 8*(g>>1), 16B-slot = g&1
    uint32_t b_row  = (uint32_t)(nw * 32 + (lane & 7) + 8 * (g >> 1));
    uint32_t b_slot = (uint32_t)(g & 1);

    float acc[2][4][4];
#pragma unroll
    for (int i = 0; i < 2; i++)
#pragma unroll
        for (int j = 0; j < 4; j++)
#pragma unroll
            for (int e = 0; e < 4; e++) acc[i][j][e] = 0.f;

    auto issue = [&](int c, uint32_t st) {
        if (c < NCHUNK) {
            uint32_t c8 = (uint32_t)c * 8u;
            cpasync16(st + adst[0], ah[0] + c8);
            cpasync16(st + adst[1], ah[1] + c8);
#pragma unroll
            for (int j = 0; j < 4; j++)
                cpasync16(st + A_T + bdst[j], bw + boff[j] + c8);
        }
        CP_COMMIT();
    };

    issue(0, sb);
    issue(1, sb + STAGE_B);

    int cs = 0;   // compute stage
    int is = 2;   // issue stage
#pragma unroll 1
    for (int c = 0; c < NCHUNK; c++) {
        CP_WAIT1();
        __syncthreads();
        issue(c + 2, sb + (uint32_t)is * STAGE_B);
        uint32_t st = sb + (uint32_t)cs * STAGE_B;

#pragma unroll
        for (int ks = 0; ks < 4; ks++) {
            uint32_t ka = (uint32_t)(((2 * ks + a_slot) ^ xr) << 4);
            uint32_t kb = (uint32_t)(((2 * ks + b_slot) ^ xr) << 4);
            uint32_t Ah[2][4];
#pragma unroll
            for (int i = 0; i < 2; i++)
                ldsm4(Ah[i], st + (a_row + (uint32_t)i * 16u) * ROW_B + ka);
#pragma unroll
            for (int jp = 0; jp < 2; jp++) {
                uint32_t B[4];
                ldsm4(B, st + A_T + (b_row + (uint32_t)jp * 16u) * ROW_B + kb);
#pragma unroll
                for (int i = 0; i < 2; i++) {
                    mma_f16(acc[i][jp * 2],     Ah[i], &B[0]);
                    mma_f16(acc[i][jp * 2 + 1], Ah[i], &B[2]);
                }
            }
        }
        cs = (cs == 2) ? 0 : cs + 1;
        is = (is == 2) ? 0 : is + 1;
    }

    // ---- fused epilogue: relu(acc + b1) * W3, row-reduce, atomicAdd ----
#pragma unroll
    for (int i = 0; i < 2; i++) {
        float s0 = 0.f, s1 = 0.f;
#pragma unroll
        for (int j = 0; j < 4; j++) {
            int d = dbase + nw * 32 + j * 8 + 2 * (lane & 3);
            float bb0 = __ldg(&b1[(size_t)d * NK + k]);
            float bb1 = __ldg(&b1[(size_t)(d + 1) * NK + k]);
            float w30 = __ldg(&W3[d]);
            float w31 = __ldg(&W3[d + 1]);
            s0 = fmaf(fmaxf(acc[i][j][0] + bb0, 0.f), w30, s0);
            s0 = fmaf(fmaxf(acc[i][j][1] + bb1, 0.f), w31, s0);
            s1 = fmaf(fmaxf(acc[i][j][2] + bb0, 0.f), w30, s1);
            s1 = fmaf(fmaxf(acc[i][j][3] + bb1, 0.f), w31, s1);
        }
        s0 += __shfl_xor_sync(0xFFFFFFFFu, s0, 1);
        s0 += __shfl_xor_sync(0xFFFFFFFFu, s0, 2);
        s1 += __shfl_xor_sync(0xFFFFFFFFu, s1, 1);
        s1 += __shfl_xor_sync(0xFFFFFFFFu, s1, 2);
        if ((lane & 3) == 0) {
            int m0 = mw * 32 + i * 16 + (lane >> 2);
            int pr0 = row0 + m0;
            int pr1 = pr0 + 8;
            if (pr0 < rend) atomicAdd(&out[g_perm[pr0]], s0);
            if (pr1 < rend) atomicAdd(&out[g_perm[pr1]], s1);
        }
    }
}

// ---------------- launch ----------------
extern "C" void kernel_launch(void* const* d_in, const int* in_sizes, int n_in,
                              void* d_out, int out_size) {
    const float* x         = (const float*)d_in[0];
    const float* intention = (const float*)d_in[1];
    const float* W1        = (const float*)d_in[2];
    const float* b1        = (const float*)d_in[3];
    const float* W2        = (const float*)d_in[4];
    const float* b2        = (const float*)d_in[5];
    const float* W3        = (const float*)d_in[6];
    const float* b3        = (const float*)d_in[7];
    float* out             = (float*)d_out;

    cudaFuncSetAttribute(gemm_kernel, cudaFuncAttributeMaxDynamicSharedMemorySize,
                         SMEM_TOTAL);

    prep_kernel<<<1, 1024>>>(intention, W2, b2, W3, b3, out);
    cvt_kernel<<<BATCH + DIM * NK, 256>>>(x, W1);
    gemm_kernel<<<dim3(GYT, GX), 256, SMEM_TOTAL>>>(b1, W3, out);
}